// round 3
// baseline (speedup 1.0000x reference)
#include <cuda_runtime.h>
#include <cstdint>

// Problem constants: SEQ=1024, BATCH=512, IN=128, HID=256, alpha=0.2
#define S_  1024
#define B_  512
#define IN_ 128
#define H_  256

typedef unsigned long long u64;

__device__ __forceinline__ u64 ffma2(u64 a, u64 b, u64 c) {
    u64 d;
    asm("fma.rn.f32x2 %0, %1, %2, %3;" : "=l"(d) : "l"(a), "l"(b), "l"(c));
    return d;
}
__device__ __forceinline__ u64 pack2(float x, float y) {
    u64 r;
    asm("mov.b64 %0, {%1, %2};" : "=l"(r) : "f"(x), "f"(y));
    return r;
}
__device__ __forceinline__ float2 unpack2(u64 v) {
    float2 r;
    asm("mov.b64 {%0, %1}, %2;" : "=f"(r.x), "=f"(r.y) : "l"(v));
    return r;
}

// ======================= Phase 1: x_proj GEMM ============================
// out[(s*B + b)*H + h] = input[s,b,:] . W_in[:,h] + b_in[h] + b_hh[h]
// Treated as [M=524288, K=128] @ [128, 256].  Block tile: 128 rows x 128 cols,
// 256 threads, thread micro-tile 8x8, all FMAs as packed f32x2 over row pairs.
// B tile stored duplicated (w,w) in smem so f32x2 operands load directly.

#define XP_ASTRIDE 132
#define XP_SMEM ((128 * XP_ASTRIDE + 128 * 256) * 4)   // 198656 B

__global__ void __launch_bounds__(256, 1) xproj_kernel(
    const float* __restrict__ input, const float* __restrict__ Win,
    const float* __restrict__ bin, const float* __restrict__ bhh,
    float* __restrict__ out)
{
    extern __shared__ float sm[];
    float* As  = sm;                       // transposed A tile: [k][m], stride 132
    float* Bs2 = sm + 128 * XP_ASTRIDE;    // dup B tile: float2 per (k,n): off k*256+2n
    const int t = threadIdx.x;
    const size_t rowBase = (size_t)blockIdx.x * 128;
    const int colBase = blockIdx.y * 128;

    // Stage A tile (128 rows x 128 k), transposed into smem.
    {
        int r = t >> 1, k0 = (t & 1) * 64;
        const float4* src = (const float4*)(input + (rowBase + r) * IN_ + k0);
        #pragma unroll
        for (int i = 0; i < 16; i++) {
            float4 v = src[i];
            int k = k0 + i * 4;
            As[(k + 0) * XP_ASTRIDE + r] = v.x;
            As[(k + 1) * XP_ASTRIDE + r] = v.y;
            As[(k + 2) * XP_ASTRIDE + r] = v.z;
            As[(k + 3) * XP_ASTRIDE + r] = v.w;
        }
    }
    // Stage B tile (128 k x 128 n) duplicated into lane pairs.
    {
        int k = t >> 1, n0 = (t & 1) * 64;
        const float4* src = (const float4*)(Win + (size_t)k * H_ + colBase + n0);
        float2* dst = (float2*)(Bs2 + k * 256 + n0 * 2);
        #pragma unroll
        for (int i = 0; i < 16; i++) {
            float4 v = src[i];
            dst[i * 4 + 0] = make_float2(v.x, v.x);
            dst[i * 4 + 1] = make_float2(v.y, v.y);
            dst[i * 4 + 2] = make_float2(v.z, v.z);
            dst[i * 4 + 3] = make_float2(v.w, v.w);
        }
    }
    __syncthreads();

    const int tx = t & 15, ty = t >> 4;
    const int m0 = ty * 8, n0 = tx * 8;

    u64 acc[4][8];   // [row-pair][col]
    #pragma unroll
    for (int jj = 0; jj < 8; jj++) {
        float bias = bin[colBase + n0 + jj] + bhh[colBase + n0 + jj];
        u64 bb = pack2(bias, bias);
        #pragma unroll
        for (int mp = 0; mp < 4; mp++) acc[mp][jj] = bb;
    }

    #pragma unroll 4
    for (int k = 0; k < 128; k++) {
        const ulonglong2* ap = (const ulonglong2*)(As + k * XP_ASTRIDE + m0);
        ulonglong2 a01 = ap[0], a23 = ap[1];
        u64 av[4] = {a01.x, a01.y, a23.x, a23.y};
        const ulonglong2* bp = (const ulonglong2*)(Bs2 + k * 256 + n0 * 2);
        ulonglong2 b01 = bp[0], b23 = bp[1], b45 = bp[2], b67 = bp[3];
        u64 bv[8] = {b01.x, b01.y, b23.x, b23.y, b45.x, b45.y, b67.x, b67.y};
        #pragma unroll
        for (int mp = 0; mp < 4; mp++)
            #pragma unroll
            for (int jj = 0; jj < 8; jj++)
                acc[mp][jj] = ffma2(av[mp], bv[jj], acc[mp][jj]);
    }

    // Writeout: row pair (m0+2mp, m0+2mp+1), cols n0..n0+7, float4 stores.
    #pragma unroll
    for (int mp = 0; mp < 4; mp++) {
        float v0[8], v1[8];
        #pragma unroll
        for (int jj = 0; jj < 8; jj++) {
            float2 p = unpack2(acc[mp][jj]);
            v0[jj] = p.x; v1[jj] = p.y;
        }
        float* o0 = out + (rowBase + m0 + 2 * mp) * (size_t)H_ + colBase + n0;
        float* o1 = o0 + H_;
        ((float4*)o0)[0] = make_float4(v0[0], v0[1], v0[2], v0[3]);
        ((float4*)o0)[1] = make_float4(v0[4], v0[5], v0[6], v0[7]);
        ((float4*)o1)[0] = make_float4(v1[0], v1[1], v1[2], v1[3]);
        ((float4*)o1)[1] = make_float4(v1[4], v1[5], v1[6], v1[7]);
    }
}

// ======================= Phase 2: recurrence =============================
// 128 persistent blocks x 256 threads. Block owns 4 batch rows for all 1024
// steps. Thread j owns output column j. W_hh split: k=0..127 in registers
// (f32x2 pairs), k=128..255 in smem as per-column float4 groups. h double
// buffered in smem; one __syncthreads per step. xp read from d_out and the
// same address overwritten with h_new.

#define RC_SMEM ((32 * 256 * 4 + 2 * 4 * 256) * 4)     // 139264 B

__global__ void __launch_bounds__(256, 1) ctrnn_rec_kernel(
    const float* __restrict__ hidden, const float* __restrict__ Whh,
    float* __restrict__ out, float* __restrict__ tail)
{
    extern __shared__ float sm[];
    float* Ws = sm;                 // float4 per (k4, j): float offset (k4*256+j)*4
    float* hb = sm + 32 * 256 * 4;  // h[2][4][256]
    const int j = threadIdx.x;
    const int b0 = blockIdx.x * 4;

    // W registers: rows k=0..127, column j, packed as k-pairs.
    u64 Wreg[64];
    #pragma unroll
    for (int p = 0; p < 64; p++) {
        float w0 = Whh[(2 * p) * H_ + j];
        float w1 = Whh[(2 * p + 1) * H_ + j];
        Wreg[p] = pack2(w0, w1);
    }
    // W smem: rows k=128..255 as per-column float4 (4 consecutive k).
    for (int k4 = 0; k4 < 32; k4++) {
        float4 v;
        v.x = Whh[(128 + 4 * k4 + 0) * H_ + j];
        v.y = Whh[(128 + 4 * k4 + 1) * H_ + j];
        v.z = Whh[(128 + 4 * k4 + 2) * H_ + j];
        v.w = Whh[(128 + 4 * k4 + 3) * H_ + j];
        ((float4*)Ws)[k4 * 256 + j] = v;
    }
    // Initial hidden state.
    #pragma unroll
    for (int b = 0; b < 4; b++)
        hb[b * 256 + j] = hidden[(b0 + b) * H_ + j];
    __syncthreads();

    for (int s = 0; s < S_; s++) {
        const float* hc = hb + (s & 1) * 1024;
        float* hn = hb + ((s & 1) ^ 1) * 1024;
        float* op = out + ((size_t)s * B_ + b0) * H_ + j;
        float xp0 = op[0], xp1 = op[256], xp2 = op[512], xp3 = op[768];

        u64 acc0 = 0ULL, acc1 = 0ULL, acc2 = 0ULL, acc3 = 0ULL;

        // k = 0..127: W from registers, h broadcast from smem (f32x2 k-pairs).
        #pragma unroll 4
        for (int k4 = 0; k4 < 32; k4++) {
            ulonglong2 h0 = *(const ulonglong2*)(hc + 0 * 256 + k4 * 4);
            ulonglong2 h1 = *(const ulonglong2*)(hc + 1 * 256 + k4 * 4);
            ulonglong2 h2 = *(const ulonglong2*)(hc + 2 * 256 + k4 * 4);
            ulonglong2 h3 = *(const ulonglong2*)(hc + 3 * 256 + k4 * 4);
            u64 w0 = Wreg[2 * k4], w1 = Wreg[2 * k4 + 1];
            acc0 = ffma2(h0.x, w0, acc0); acc0 = ffma2(h0.y, w1, acc0);
            acc1 = ffma2(h1.x, w0, acc1); acc1 = ffma2(h1.y, w1, acc1);
            acc2 = ffma2(h2.x, w0, acc2); acc2 = ffma2(h2.y, w1, acc2);
            acc3 = ffma2(h3.x, w0, acc3); acc3 = ffma2(h3.y, w1, acc3);
        }
        // k = 128..255: W from smem float4 (one conflict-free LDS.128 per 4 k).
        #pragma unroll 4
        for (int k4 = 0; k4 < 32; k4++) {
            ulonglong2 wv = *(const ulonglong2*)(Ws + (k4 * 256 + j) * 4);
            ulonglong2 h0 = *(const ulonglong2*)(hc + 128 + 0 * 256 + k4 * 4);
            ulonglong2 h1 = *(const ulonglong2*)(hc + 128 + 1 * 256 + k4 * 4);
            ulonglong2 h2 = *(const ulonglong2*)(hc + 128 + 2 * 256 + k4 * 4);
            ulonglong2 h3 = *(const ulonglong2*)(hc + 128 + 3 * 256 + k4 * 4);
            acc0 = ffma2(h0.x, wv.x, acc0); acc0 = ffma2(h0.y, wv.y, acc0);
            acc1 = ffma2(h1.x, wv.x, acc1); acc1 = ffma2(h1.y, wv.y, acc1);
            acc2 = ffma2(h2.x, wv.x, acc2); acc2 = ffma2(h2.y, wv.y, acc2);
            acc3 = ffma2(h3.x, wv.x, acc3); acc3 = ffma2(h3.y, wv.y, acc3);
        }

        float2 p0 = unpack2(acc0), p1 = unpack2(acc1);
        float2 p2 = unpack2(acc2), p3 = unpack2(acc3);
        float pre0 = xp0 + p0.x + p0.y;
        float pre1 = xp1 + p1.x + p1.y;
        float pre2 = xp2 + p2.x + p2.y;
        float pre3 = xp3 + p3.x + p3.y;

        float ho0 = hc[0 * 256 + j], ho1 = hc[1 * 256 + j];
        float ho2 = hc[2 * 256 + j], ho3 = hc[3 * 256 + j];
        float hn0 = 0.8f * ho0 + 0.2f * fmaxf(pre0, 0.0f);
        float hn1 = 0.8f * ho1 + 0.2f * fmaxf(pre1, 0.0f);
        float hn2 = 0.8f * ho2 + 0.2f * fmaxf(pre2, 0.0f);
        float hn3 = 0.8f * ho3 + 0.2f * fmaxf(pre3, 0.0f);

        hn[0 * 256 + j] = hn0; hn[1 * 256 + j] = hn1;
        hn[2 * 256 + j] = hn2; hn[3 * 256 + j] = hn3;
        op[0] = hn0; op[256] = hn1; op[512] = hn2; op[768] = hn3;

        __syncthreads();
    }

    if (tail) {
        // Final h sits in buffer 0 (last step s=1023 wrote buffer (1023&1)^1 = 0).
        // Each thread reads only its own previously-written values.
        #pragma unroll
        for (int b = 0; b < 4; b++)
            tail[(size_t)(b0 + b) * H_ + j] = hb[b * 256 + j];
    }
}

// ============================== launch ===================================

extern "C" void kernel_launch(void* const* d_in, const int* in_sizes, int n_in,
                              void* d_out, int out_size) {
    const float* input  = (const float*)d_in[0];
    const float* hidden = (const float*)d_in[1];
    const float* Win    = (const float*)d_in[2];
    const float* bin    = (const float*)d_in[3];
    const float* Whh    = (const float*)d_in[4];
    const float* bhh    = (const float*)d_in[5];
    float* out = (float*)d_out;

    cudaFuncSetAttribute(xproj_kernel,
                         cudaFuncAttributeMaxDynamicSharedMemorySize, XP_SMEM);
    cudaFuncSetAttribute(ctrnn_rec_kernel,
                         cudaFuncAttributeMaxDynamicSharedMemorySize, RC_SMEM);

    dim3 g(4096, 2);
    xproj_kernel<<<g, 256, XP_SMEM>>>(input, Win, bin, bhh, out);

    long long main_elems = (long long)S_ * B_ * H_;
    float* tail = ((long long)out_size > main_elems) ? (out + main_elems) : nullptr;
    ctrnn_rec_kernel<<<128, 256, RC_SMEM>>>(hidden, Whh, out, tail);
}

// round 4
// speedup vs baseline: 1.1407x; 1.1407x over previous
#include <cuda_runtime.h>
#include <cstdint>

// Problem constants: SEQ=1024, BATCH=512, IN=128, HID=256, alpha=0.2
#define S_  1024
#define B_  512
#define IN_ 128
#define H_  256

typedef unsigned long long u64;

__device__ __forceinline__ u64 ffma2(u64 a, u64 b, u64 c) {
    u64 d;
    asm("fma.rn.f32x2 %0, %1, %2, %3;" : "=l"(d) : "l"(a), "l"(b), "l"(c));
    return d;
}
__device__ __forceinline__ u64 pack2(float x, float y) {
    u64 r;
    asm("mov.b64 %0, {%1, %2};" : "=l"(r) : "f"(x), "f"(y));
    return r;
}
__device__ __forceinline__ float2 unpack2(u64 v) {
    float2 r;
    asm("mov.b64 {%0, %1}, %2;" : "=f"(r.x), "=f"(r.y) : "l"(v));
    return r;
}

// ======================= Phase 1: x_proj GEMM ============================
// out[(s*B + b)*H + h] = input[s,b,:] . W_in[:,h] + b_in[h] + b_hh[h]
// [M=524288, K=128] @ [128, 256].  Block tile 128x128, 256 threads,
// thread micro-tile 8x8, packed f32x2 over row pairs; B tile duplicated.

#define XP_ASTRIDE 132
#define XP_SMEM ((128 * XP_ASTRIDE + 128 * 256) * 4)   // 198656 B

__global__ void __launch_bounds__(256, 1) xproj_kernel(
    const float* __restrict__ input, const float* __restrict__ Win,
    const float* __restrict__ bin, const float* __restrict__ bhh,
    float* __restrict__ out)
{
    extern __shared__ float sm[];
    float* As  = sm;                       // transposed A tile: [k][m], stride 132
    float* Bs2 = sm + 128 * XP_ASTRIDE;    // dup B tile: float2 per (k,n)
    const int t = threadIdx.x;
    const size_t rowBase = (size_t)blockIdx.x * 128;
    const int colBase = blockIdx.y * 128;

    {
        int r = t >> 1, k0 = (t & 1) * 64;
        const float4* src = (const float4*)(input + (rowBase + r) * IN_ + k0);
        #pragma unroll
        for (int i = 0; i < 16; i++) {
            float4 v = src[i];
            int k = k0 + i * 4;
            As[(k + 0) * XP_ASTRIDE + r] = v.x;
            As[(k + 1) * XP_ASTRIDE + r] = v.y;
            As[(k + 2) * XP_ASTRIDE + r] = v.z;
            As[(k + 3) * XP_ASTRIDE + r] = v.w;
        }
    }
    {
        int k = t >> 1, n0 = (t & 1) * 64;
        const float4* src = (const float4*)(Win + (size_t)k * H_ + colBase + n0);
        float2* dst = (float2*)(Bs2 + k * 256 + n0 * 2);
        #pragma unroll
        for (int i = 0; i < 16; i++) {
            float4 v = src[i];
            dst[i * 4 + 0] = make_float2(v.x, v.x);
            dst[i * 4 + 1] = make_float2(v.y, v.y);
            dst[i * 4 + 2] = make_float2(v.z, v.z);
            dst[i * 4 + 3] = make_float2(v.w, v.w);
        }
    }
    __syncthreads();

    const int tx = t & 15, ty = t >> 4;
    const int m0 = ty * 8, n0 = tx * 8;

    u64 acc[4][8];
    #pragma unroll
    for (int jj = 0; jj < 8; jj++) {
        float bias = bin[colBase + n0 + jj] + bhh[colBase + n0 + jj];
        u64 bb = pack2(bias, bias);
        #pragma unroll
        for (int mp = 0; mp < 4; mp++) acc[mp][jj] = bb;
    }

    #pragma unroll 4
    for (int k = 0; k < 128; k++) {
        const ulonglong2* ap = (const ulonglong2*)(As + k * XP_ASTRIDE + m0);
        ulonglong2 a01 = ap[0], a23 = ap[1];
        u64 av[4] = {a01.x, a01.y, a23.x, a23.y};
        const ulonglong2* bp = (const ulonglong2*)(Bs2 + k * 256 + n0 * 2);
        ulonglong2 b01 = bp[0], b23 = bp[1], b45 = bp[2], b67 = bp[3];
        u64 bv[8] = {b01.x, b01.y, b23.x, b23.y, b45.x, b45.y, b67.x, b67.y};
        #pragma unroll
        for (int mp = 0; mp < 4; mp++)
            #pragma unroll
            for (int jj = 0; jj < 8; jj++)
                acc[mp][jj] = ffma2(av[mp], bv[jj], acc[mp][jj]);
    }

    #pragma unroll
    for (int mp = 0; mp < 4; mp++) {
        float v0[8], v1[8];
        #pragma unroll
        for (int jj = 0; jj < 8; jj++) {
            float2 p = unpack2(acc[mp][jj]);
            v0[jj] = p.x; v1[jj] = p.y;
        }
        float* o0 = out + (rowBase + m0 + 2 * mp) * (size_t)H_ + colBase + n0;
        float* o1 = o0 + H_;
        ((float4*)o0)[0] = make_float4(v0[0], v0[1], v0[2], v0[3]);
        ((float4*)o0)[1] = make_float4(v0[4], v0[5], v0[6], v0[7]);
        ((float4*)o1)[0] = make_float4(v1[0], v1[1], v1[2], v1[3]);
        ((float4*)o1)[1] = make_float4(v1[4], v1[5], v1[6], v1[7]);
    }
}

// ======================= Phase 2: recurrence =============================
// 128 persistent blocks x 512 threads. Block owns 4 batch rows for all 1024
// steps. Thread (j, half) owns output column j, k-range [half*128, half*128+128).
// Of those 128 k: first 32 in registers (16 u64), remaining 96 in smem.
// Halves write partial dot products to smem; combine work is split (half0 ->
// batches 0-1, half1 -> batches 2-3). Two barriers per step.
// xp read from d_out and overwritten in place with h_new.

#define RC_NSMEMG 48                                   // 48 float4-groups of 4 k-rows
#define RC_SMEM ((RC_NSMEMG * 256 * 4 + 2 * 1024 + 2 * 1024) * 4)   // 212992 B

__global__ void __launch_bounds__(512, 1) ctrnn_rec_kernel(
    const float* __restrict__ hidden, const float* __restrict__ Whh,
    float* __restrict__ out, float* __restrict__ tail)
{
    extern __shared__ float sm[];
    float* Wsm = sm;                         // [48 groups][256 j] float4
    float* hb  = sm + RC_NSMEMG * 256 * 4;   // h[2][4][256]
    float* ps  = hb + 2 * 1024;              // partial[2 halves][4][256]
    const int tid = threadIdx.x;
    const int j = tid & 255;
    const int half = tid >> 8;
    const int b0 = blockIdx.x * 4;
    const int kbase = half * 128;

    // Registers: k = kbase .. kbase+31, column j, as k-pairs.
    u64 Wreg[16];
    #pragma unroll
    for (int p = 0; p < 16; p++) {
        float w0 = Whh[(kbase + 2 * p) * H_ + j];
        float w1 = Whh[(kbase + 2 * p + 1) * H_ + j];
        Wreg[p] = pack2(w0, w1);
    }
    // Smem: k = kbase+32 .. kbase+127 as per-column float4 (4 consecutive k).
    for (int l = 0; l < 24; l++) {
        int g = half * 24 + l;
        int kr = kbase + 32 + 4 * l;
        float4 v;
        v.x = Whh[(kr + 0) * H_ + j];
        v.y = Whh[(kr + 1) * H_ + j];
        v.z = Whh[(kr + 2) * H_ + j];
        v.w = Whh[(kr + 3) * H_ + j];
        ((float4*)Wsm)[g * 256 + j] = v;
    }
    if (half == 0) {
        #pragma unroll
        for (int b = 0; b < 4; b++)
            hb[b * 256 + j] = hidden[(b0 + b) * H_ + j];
    }
    __syncthreads();

    const int cb = half * 2;     // combine batches cb, cb+1

    for (int s = 0; s < S_; s++) {
        const float* hc = hb + (s & 1) * 1024;
        float* hn = hb + ((s & 1) ^ 1) * 1024;
        float* op = out + ((size_t)s * B_ + b0) * H_ + j;

        // Prefetch xp for the two batches this half will combine.
        float xpA = op[cb * 256];
        float xpB = op[(cb + 1) * 256];

        u64 a0 = 0ULL, a1 = 0ULL, a2 = 0ULL, a3 = 0ULL;

        // Register-weight part: 8 groups of 4 k.
        #pragma unroll
        for (int g = 0; g < 8; g++) {
            int ko = kbase + 4 * g;
            ulonglong2 h0 = *(const ulonglong2*)(hc + 0 * 256 + ko);
            ulonglong2 h1 = *(const ulonglong2*)(hc + 1 * 256 + ko);
            ulonglong2 h2 = *(const ulonglong2*)(hc + 2 * 256 + ko);
            ulonglong2 h3 = *(const ulonglong2*)(hc + 3 * 256 + ko);
            u64 w0 = Wreg[2 * g], w1 = Wreg[2 * g + 1];
            a0 = ffma2(h0.x, w0, a0); a0 = ffma2(h0.y, w1, a0);
            a1 = ffma2(h1.x, w0, a1); a1 = ffma2(h1.y, w1, a1);
            a2 = ffma2(h2.x, w0, a2); a2 = ffma2(h2.y, w1, a2);
            a3 = ffma2(h3.x, w0, a3); a3 = ffma2(h3.y, w1, a3);
        }
        // Smem-weight part: 24 groups of 4 k.
        #pragma unroll 4
        for (int l = 0; l < 24; l++) {
            int ko = kbase + 32 + 4 * l;
            ulonglong2 wv = *(const ulonglong2*)(Wsm + ((half * 24 + l) * 256 + j) * 4);
            ulonglong2 h0 = *(const ulonglong2*)(hc + 0 * 256 + ko);
            ulonglong2 h1 = *(const ulonglong2*)(hc + 1 * 256 + ko);
            ulonglong2 h2 = *(const ulonglong2*)(hc + 2 * 256 + ko);
            ulonglong2 h3 = *(const ulonglong2*)(hc + 3 * 256 + ko);
            a0 = ffma2(h0.x, wv.x, a0); a0 = ffma2(h0.y, wv.y, a0);
            a1 = ffma2(h1.x, wv.x, a1); a1 = ffma2(h1.y, wv.y, a1);
            a2 = ffma2(h2.x, wv.x, a2); a2 = ffma2(h2.y, wv.y, a2);
            a3 = ffma2(h3.x, wv.x, a3); a3 = ffma2(h3.y, wv.y, a3);
        }

        float2 p0 = unpack2(a0), p1 = unpack2(a1);
        float2 p2 = unpack2(a2), p3 = unpack2(a3);
        ps[half * 1024 + 0 * 256 + j] = p0.x + p0.y;
        ps[half * 1024 + 1 * 256 + j] = p1.x + p1.y;
        ps[half * 1024 + 2 * 256 + j] = p2.x + p2.y;
        ps[half * 1024 + 3 * 256 + j] = p3.x + p3.y;
        __syncthreads();

        // Combine: each half finalizes 2 batches.
        float sA = ps[0 * 1024 + cb * 256 + j] + ps[1 * 1024 + cb * 256 + j];
        float sB = ps[0 * 1024 + (cb + 1) * 256 + j] + ps[1 * 1024 + (cb + 1) * 256 + j];
        float hoA = hc[cb * 256 + j];
        float hoB = hc[(cb + 1) * 256 + j];
        float hnA = 0.8f * hoA + 0.2f * fmaxf(xpA + sA, 0.0f);
        float hnB = 0.8f * hoB + 0.2f * fmaxf(xpB + sB, 0.0f);
        hn[cb * 256 + j] = hnA;
        hn[(cb + 1) * 256 + j] = hnB;
        op[cb * 256] = hnA;
        op[(cb + 1) * 256] = hnB;
        __syncthreads();
    }

    if (tail && half == 0) {
        // Final h sits in buffer 0 (step s=1023 wrote buffer (1023&1)^1 = 0).
        #pragma unroll
        for (int b = 0; b < 4; b++)
            tail[(size_t)(b0 + b) * H_ + j] = hb[b * 256 + j];
    }
}

// ============================== launch ===================================

extern "C" void kernel_launch(void* const* d_in, const int* in_sizes, int n_in,
                              void* d_out, int out_size) {
    const float* input  = (const float*)d_in[0];
    const float* hidden = (const float*)d_in[1];
    const float* Win    = (const float*)d_in[2];
    const float* bin    = (const float*)d_in[3];
    const float* Whh    = (const float*)d_in[4];
    const float* bhh    = (const float*)d_in[5];
    float* out = (float*)d_out;

    cudaFuncSetAttribute(xproj_kernel,
                         cudaFuncAttributeMaxDynamicSharedMemorySize, XP_SMEM);
    cudaFuncSetAttribute(ctrnn_rec_kernel,
                         cudaFuncAttributeMaxDynamicSharedMemorySize, RC_SMEM);

    dim3 g(4096, 2);
    xproj_kernel<<<g, 256, XP_SMEM>>>(input, Win, bin, bhh, out);

    long long main_elems = (long long)S_ * B_ * H_;
    float* tail = ((long long)out_size > main_elems) ? (out + main_elems) : nullptr;
    ctrnn_rec_kernel<<<128, 512, RC_SMEM>>>(hidden, Whh, out, tail);
}

// round 6
// speedup vs baseline: 1.5503x; 1.3591x over previous
#include <cuda_runtime.h>
#include <cstdint>

// Problem constants: SEQ=1024, BATCH=512, IN=128, HID=256, alpha=0.2
#define S_  1024
#define B_  512
#define IN_ 128
#define H_  256

typedef unsigned long long u64;

__device__ __forceinline__ u64 ffma2(u64 a, u64 b, u64 c) {
    u64 d;
    asm("fma.rn.f32x2 %0, %1, %2, %3;" : "=l"(d) : "l"(a), "l"(b), "l"(c));
    return d;
}
__device__ __forceinline__ u64 pack2(float x, float y) {
    u64 r;
    asm("mov.b64 %0, {%1, %2};" : "=l"(r) : "f"(x), "f"(y));
    return r;
}
__device__ __forceinline__ float2 unpack2(u64 v) {
    float2 r;
    asm("mov.b64 {%0, %1}, %2;" : "=f"(r.x), "=f"(r.y) : "l"(v));
    return r;
}

// ======================= Phase 1: x_proj GEMM ============================
// out[(s*B + b)*H + h] = input[s,b,:] . W_in[:,h] + b_in[h] + b_hh[h]
// [M=524288, K=128] @ [128, 256].  Block tile 128x128, 256 threads,
// thread micro-tile 8x8, packed f32x2 over row pairs; B tile duplicated.

#define XP_ASTRIDE 132
#define XP_SMEM ((128 * XP_ASTRIDE + 128 * 256) * 4)   // 198656 B

__global__ void __launch_bounds__(256, 1) xproj_kernel(
    const float* __restrict__ input, const float* __restrict__ Win,
    const float* __restrict__ bin, const float* __restrict__ bhh,
    float* __restrict__ out)
{
    extern __shared__ float sm[];
    float* As  = sm;                       // transposed A tile: [k][m], stride 132
    float* Bs2 = sm + 128 * XP_ASTRIDE;    // dup B tile: float2 per (k,n)
    const int t = threadIdx.x;
    const size_t rowBase = (size_t)blockIdx.x * 128;
    const int colBase = blockIdx.y * 128;

    {
        int r = t >> 1, k0 = (t & 1) * 64;
        const float4* src = (const float4*)(input + (rowBase + r) * IN_ + k0);
        #pragma unroll
        for (int i = 0; i < 16; i++) {
            float4 v = src[i];
            int k = k0 + i * 4;
            As[(k + 0) * XP_ASTRIDE + r] = v.x;
            As[(k + 1) * XP_ASTRIDE + r] = v.y;
            As[(k + 2) * XP_ASTRIDE + r] = v.z;
            As[(k + 3) * XP_ASTRIDE + r] = v.w;
        }
    }
    {
        int k = t >> 1, n0 = (t & 1) * 64;
        const float4* src = (const float4*)(Win + (size_t)k * H_ + colBase + n0);
        float2* dst = (float2*)(Bs2 + k * 256 + n0 * 2);
        #pragma unroll
        for (int i = 0; i < 16; i++) {
            float4 v = src[i];
            dst[i * 4 + 0] = make_float2(v.x, v.x);
            dst[i * 4 + 1] = make_float2(v.y, v.y);
            dst[i * 4 + 2] = make_float2(v.z, v.z);
            dst[i * 4 + 3] = make_float2(v.w, v.w);
        }
    }
    __syncthreads();

    const int tx = t & 15, ty = t >> 4;
    const int m0 = ty * 8, n0 = tx * 8;

    u64 acc[4][8];
    #pragma unroll
    for (int jj = 0; jj < 8; jj++) {
        float bias = bin[colBase + n0 + jj] + bhh[colBase + n0 + jj];
        u64 bb = pack2(bias, bias);
        #pragma unroll
        for (int mp = 0; mp < 4; mp++) acc[mp][jj] = bb;
    }

    #pragma unroll 4
    for (int k = 0; k < 128; k++) {
        const ulonglong2* ap = (const ulonglong2*)(As + k * XP_ASTRIDE + m0);
        ulonglong2 a01 = ap[0], a23 = ap[1];
        u64 av[4] = {a01.x, a01.y, a23.x, a23.y};
        const ulonglong2* bp = (const ulonglong2*)(Bs2 + k * 256 + n0 * 2);
        ulonglong2 b01 = bp[0], b23 = bp[1], b45 = bp[2], b67 = bp[3];
        u64 bv[8] = {b01.x, b01.y, b23.x, b23.y, b45.x, b45.y, b67.x, b67.y};
        #pragma unroll
        for (int mp = 0; mp < 4; mp++)
            #pragma unroll
            for (int jj = 0; jj < 8; jj++)
                acc[mp][jj] = ffma2(av[mp], bv[jj], acc[mp][jj]);
    }

    #pragma unroll
    for (int mp = 0; mp < 4; mp++) {
        float v0[8], v1[8];
        #pragma unroll
        for (int jj = 0; jj < 8; jj++) {
            float2 p = unpack2(acc[mp][jj]);
            v0[jj] = p.x; v1[jj] = p.y;
        }
        float* o0 = out + (rowBase + m0 + 2 * mp) * (size_t)H_ + colBase + n0;
        float* o1 = o0 + H_;
        ((float4*)o0)[0] = make_float4(v0[0], v0[1], v0[2], v0[3]);
        ((float4*)o0)[1] = make_float4(v0[4], v0[5], v0[6], v0[7]);
        ((float4*)o1)[0] = make_float4(v1[0], v1[1], v1[2], v1[3]);
        ((float4*)o1)[1] = make_float4(v1[4], v1[5], v1[6], v1[7]);
    }
}

// ======================= Phase 2: recurrence =============================
// 128 persistent blocks x 512 threads, 4 batches per block.
// h batch-major in smem: hs[k] = float4(h[k, b0..b3]); one broadcast LDS.128
// per k gives both batch-pairs pre-packed for f32x2 FMA.
// Thread (jg = t&63, c = t>>6) owns cols {4jg..4jg+3}, k-range [32c, 32c+32):
//   k-rows 0..15: W in registers as UNDUP float4 (64 regs), dup'ed on ALU
//   k-rows 16..31: W in smem float4 (4 cols), dup'ed on ALU
// Partials exchanged as scalar floats ps[c][b][col]: stores are lane-
// consecutive STS.128, reads lane-consecutive LDS.32 — both conflict-free.

#define RC_CH    8
#define RC_KR    32
#define RC_KREG  16
#define RC_KSM   16
#define RC_WSM_BYTES (RC_CH * RC_KSM * 64 * 16)   // 131072
#define RC_HS_BYTES  (2 * 256 * 4 * 4)            // 8192
#define RC_PS_BYTES  (RC_CH * 4 * 256 * 4)        // 32768
#define RC_SMEM (RC_WSM_BYTES + RC_HS_BYTES + RC_PS_BYTES)   // 172032

__global__ void __launch_bounds__(512, 1) ctrnn_rec_kernel(
    const float* __restrict__ hidden, const float* __restrict__ Whh,
    float* __restrict__ out, float* __restrict__ tail)
{
    extern __shared__ char smc[];
    float4* Wsm = (float4*)smc;                                // [128][64]
    float*  hsb = (float*)(smc + RC_WSM_BYTES);                // [2][256][4]
    float*  psb = (float*)(smc + RC_WSM_BYTES + RC_HS_BYTES);  // [8][4][256]
    const int t  = threadIdx.x;
    const int jg = t & 63;
    const int c  = t >> 6;
    const int col = t & 255;
    const int hf  = t >> 8;
    const int b0 = blockIdx.x * 4;
    const int k0 = c * RC_KR;

    // --- prologue: weights ---
    float4 wreg[RC_KREG];                 // rows k0..k0+15, cols 4jg..4jg+3
    #pragma unroll
    for (int i = 0; i < RC_KREG; i++)
        wreg[i] = *(const float4*)(Whh + (size_t)(k0 + i) * H_ + 4 * jg);
    #pragma unroll
    for (int i = 0; i < RC_KSM; i++)
        Wsm[(c * RC_KSM + i) * 64 + jg] =
            *(const float4*)(Whh + (size_t)(k0 + RC_KREG + i) * H_ + 4 * jg);
    // --- prologue: h0, batch-major ---
    if (t < 256) {
        float4 v;
        v.x = hidden[(b0 + 0) * H_ + t];
        v.y = hidden[(b0 + 1) * H_ + t];
        v.z = hidden[(b0 + 2) * H_ + t];
        v.w = hidden[(b0 + 3) * H_ + t];
        ((float4*)hsb)[t] = v;
    }
    __syncthreads();

    const int bA = 2 * hf, bB = 2 * hf + 1;

    for (int s = 0; s < S_; s++) {
        const float* hc = hsb + (s & 1) * 1024;
        float* hn = hsb + ((s & 1) ^ 1) * 1024;
        float* op = out + ((size_t)s * B_ + b0) * H_ + col;

        // Prefetch xp for the two batches this thread combines (consumed
        // after the barrier — DRAM latency fully hidden under the GEMM).
        float xpA = op[bA * 256];
        float xpB = op[bB * 256];

        const ulonglong2* hc2 = (const ulonglong2*)hc;   // hc2[k] = (b01, b23)
        u64 acc[4][2];
        #pragma unroll
        for (int cc = 0; cc < 4; cc++) { acc[cc][0] = 0ULL; acc[cc][1] = 0ULL; }

        // Register-weight rows (dup on ALU).
        #pragma unroll
        for (int i = 0; i < RC_KREG; i++) {
            ulonglong2 hv = hc2[k0 + i];
            float4 w4 = wreg[i];
            u64 w0 = pack2(w4.x, w4.x), w1 = pack2(w4.y, w4.y);
            u64 w2 = pack2(w4.z, w4.z), w3 = pack2(w4.w, w4.w);
            acc[0][0] = ffma2(hv.x, w0, acc[0][0]);
            acc[0][1] = ffma2(hv.y, w0, acc[0][1]);
            acc[1][0] = ffma2(hv.x, w1, acc[1][0]);
            acc[1][1] = ffma2(hv.y, w1, acc[1][1]);
            acc[2][0] = ffma2(hv.x, w2, acc[2][0]);
            acc[2][1] = ffma2(hv.y, w2, acc[2][1]);
            acc[3][0] = ffma2(hv.x, w3, acc[3][0]);
            acc[3][1] = ffma2(hv.y, w3, acc[3][1]);
        }
        // Smem-weight rows (conflict-free LDS.128, dup on ALU).
        #pragma unroll
        for (int i = 0; i < RC_KSM; i++) {
            float4 w4 = Wsm[(c * RC_KSM + i) * 64 + jg];
            ulonglong2 hv = hc2[k0 + RC_KREG + i];
            u64 w0 = pack2(w4.x, w4.x), w1 = pack2(w4.y, w4.y);
            u64 w2 = pack2(w4.z, w4.z), w3 = pack2(w4.w, w4.w);
            acc[0][0] = ffma2(hv.x, w0, acc[0][0]);
            acc[0][1] = ffma2(hv.y, w0, acc[0][1]);
            acc[1][0] = ffma2(hv.x, w1, acc[1][0]);
            acc[1][1] = ffma2(hv.y, w1, acc[1][1]);
            acc[2][0] = ffma2(hv.x, w2, acc[2][0]);
            acc[2][1] = ffma2(hv.y, w2, acc[2][1]);
            acc[3][0] = ffma2(hv.x, w3, acc[3][0]);
            acc[3][1] = ffma2(hv.y, w3, acc[3][1]);
        }

        // Partials: ps[c][b][col], per-batch float4 stores at 4*jg
        // (lane-consecutive, conflict-free).
        {
            float2 u0a = unpack2(acc[0][0]), u1a = unpack2(acc[1][0]);
            float2 u2a = unpack2(acc[2][0]), u3a = unpack2(acc[3][0]);
            float2 u0b = unpack2(acc[0][1]), u1b = unpack2(acc[1][1]);
            float2 u2b = unpack2(acc[2][1]), u3b = unpack2(acc[3][1]);
            *(float4*)(psb + (c * 4 + 0) * 256 + 4 * jg) =
                make_float4(u0a.x, u1a.x, u2a.x, u3a.x);
            *(float4*)(psb + (c * 4 + 1) * 256 + 4 * jg) =
                make_float4(u0a.y, u1a.y, u2a.y, u3a.y);
            *(float4*)(psb + (c * 4 + 2) * 256 + 4 * jg) =
                make_float4(u0b.x, u1b.x, u2b.x, u3b.x);
            *(float4*)(psb + (c * 4 + 3) * 256 + 4 * jg) =
                make_float4(u0b.y, u1b.y, u2b.y, u3b.y);
        }
        __syncthreads();

        // Combine: thread (col, hf) finalizes batches bA, bB of its col.
        {
            float sA = 0.0f, sB = 0.0f;
            #pragma unroll
            for (int cc = 0; cc < RC_CH; cc++) {
                sA += psb[(cc * 4 + bA) * 256 + col];
                sB += psb[(cc * 4 + bB) * 256 + col];
            }
            float hoA = hc[col * 4 + bA];
            float hoB = hc[col * 4 + bB];
            float hnA = 0.8f * hoA + 0.2f * fmaxf(xpA + sA, 0.0f);
            float hnB = 0.8f * hoB + 0.2f * fmaxf(xpB + sB, 0.0f);
            hn[col * 4 + bA] = hnA;
            hn[col * 4 + bB] = hnB;
            op[bA * 256] = hnA;
            op[bB * 256] = hnB;
        }
        __syncthreads();
    }

    if (tail) {
        // Final h sits in buffer 0 (step s=1023 wrote buffer (1023&1)^1 = 0).
        tail[(size_t)(b0 + bA) * H_ + col] = hsb[col * 4 + bA];
        tail[(size_t)(b0 + bB) * H_ + col] = hsb[col * 4 + bB];
    }
}

// ============================== launch ===================================

extern "C" void kernel_launch(void* const* d_in, const int* in_sizes, int n_in,
                              void* d_out, int out_size) {
    const float* input  = (const float*)d_in[0];
    const float* hidden = (const float*)d_in[1];
    const float* Win    = (const float*)d_in[2];
    const float* bin    = (const float*)d_in[3];
    const float* Whh    = (const float*)d_in[4];
    const float* bhh    = (const float*)d_in[5];
    float* out = (float*)d_out;

    cudaFuncSetAttribute(xproj_kernel,
                         cudaFuncAttributeMaxDynamicSharedMemorySize, XP_SMEM);
    cudaFuncSetAttribute(ctrnn_rec_kernel,
                         cudaFuncAttributeMaxDynamicSharedMemorySize, RC_SMEM);

    dim3 g(4096, 2);
    xproj_kernel<<<g, 256, XP_SMEM>>>(input, Win, bin, bhh, out);

    long long main_elems = (long long)S_ * B_ * H_;
    float* tail = ((long long)out_size > main_elems) ? (out + main_elems) : nullptr;
    ctrnn_rec_kernel<<<128, 512, RC_SMEM>>>(hidden, Whh, out, tail);
}

// round 10
// speedup vs baseline: 2.7641x; 1.7829x over previous
#include <cuda_runtime.h>
#include <cstdint>

// Problem constants: SEQ=1024, BATCH=512, IN=128, HID=256, alpha=0.2
#define S_  1024
#define B_  512
#define IN_ 128
#define H_  256

typedef unsigned long long u64;

__device__ __forceinline__ u64 ffma2(u64 a, u64 b, u64 c) {
    u64 d;
    asm("fma.rn.f32x2 %0, %1, %2, %3;" : "=l"(d) : "l"(a), "l"(b), "l"(c));
    return d;
}
__device__ __forceinline__ u64 pack2(float x, float y) {
    u64 r;
    asm("mov.b64 %0, {%1, %2};" : "=l"(r) : "f"(x), "f"(y));
    return r;
}
__device__ __forceinline__ float2 unpack2(u64 v) {
    float2 r;
    asm("mov.b64 {%0, %1}, %2;" : "=f"(r.x), "=f"(r.y) : "l"(v));
    return r;
}

// ======================= Phase 1: x_proj GEMM ============================
// out[(s*B + b)*H + h] = input[s,b,:] . W_in[:,h] + b_in[h] + b_hh[h]
// [M=524288, K=128] @ [128, 256].
// v2: chunked-K (KC=16, 8 chunks) double-buffered; block tile 128x64,
// 256 threads, thread tile 4 row-pairs x 4 cols (f32x2). Static smem 25KB,
// __launch_bounds__(256,3) -> 3 blocks/SM (24 warps, 6/SMSP). LDG of the
// next chunk is issued before computing the current one.

#define XP_KC   16
#define XP_AST  132     // padded row stride of transposed A chunk

__global__ void __launch_bounds__(256, 3) xproj_kernel(
    const float* __restrict__ input, const float* __restrict__ Win,
    const float* __restrict__ bin, const float* __restrict__ bhh,
    float* __restrict__ out)
{
    __shared__ float As[2][XP_KC][XP_AST];   // transposed A: [k][m], 16896 B
    __shared__ float Bs[2][XP_KC][64];       // B chunk: [k][n], 8192 B

    const int t = threadIdx.x;
    const size_t rowBase = (size_t)blockIdx.x * 128;
    const int colBase = blockIdx.y * 64;

    const int tx = t & 15, ty = t >> 4;
    const int m0 = ty * 8, n0 = tx * 4;

    // Staging indices
    const int rA = t >> 2;          // rows rA and rA+64
    const int kq = t & 3;           // float4 index within the 16-k chunk
    const int bk = t >> 4;          // B: k row
    const int bn = (t & 15) * 4;    // B: col group

    const float* aSrc0 = input + (rowBase + rA) * IN_ + kq * 4;
    const float* aSrc1 = input + (rowBase + rA + 64) * IN_ + kq * 4;
    const float* bSrc  = Win + (size_t)bk * H_ + colBase + bn;

    // acc init with bias
    u64 acc[4][4];
    {
        float4 bi = *(const float4*)(bin + colBase + n0);
        float4 bh = *(const float4*)(bhh + colBase + n0);
        float bias[4] = {bi.x + bh.x, bi.y + bh.y, bi.z + bh.z, bi.w + bh.w};
        #pragma unroll
        for (int j = 0; j < 4; j++) {
            u64 bb = pack2(bias[j], bias[j]);
            #pragma unroll
            for (int mp = 0; mp < 4; mp++) acc[mp][j] = bb;
        }
    }

    // Prologue: stage chunk 0.
    {
        float4 a0 = *(const float4*)(aSrc0);
        float4 a1 = *(const float4*)(aSrc1);
        float4 b  = *(const float4*)(bSrc);
        #pragma unroll
        for (int j = 0; j < 4; j++) {
            As[0][kq * 4 + j][rA]      = ((const float*)&a0)[j];
            As[0][kq * 4 + j][rA + 64] = ((const float*)&a1)[j];
        }
        *(float4*)&Bs[0][bk][bn] = b;
    }
    __syncthreads();

    #pragma unroll 1
    for (int c = 0; c < 8; c++) {
        const int cur = c & 1, nxt = cur ^ 1;
        float4 a0, a1, b;
        if (c < 7) {
            a0 = *(const float4*)(aSrc0 + (c + 1) * XP_KC);
            a1 = *(const float4*)(aSrc1 + (c + 1) * XP_KC);
            b  = *(const float4*)(bSrc + (size_t)(c + 1) * XP_KC * H_);
        }

        #pragma unroll
        for (int k = 0; k < XP_KC; k++) {
            ulonglong2 ap0 = *(const ulonglong2*)&As[cur][k][m0];
            ulonglong2 ap1 = *(const ulonglong2*)&As[cur][k][m0 + 4];
            u64 av[4] = {ap0.x, ap0.y, ap1.x, ap1.y};
            float4 b4 = *(const float4*)&Bs[cur][k][n0];
            u64 bv0 = pack2(b4.x, b4.x), bv1 = pack2(b4.y, b4.y);
            u64 bv2 = pack2(b4.z, b4.z), bv3 = pack2(b4.w, b4.w);
            #pragma unroll
            for (int mp = 0; mp < 4; mp++) {
                acc[mp][0] = ffma2(av[mp], bv0, acc[mp][0]);
                acc[mp][1] = ffma2(av[mp], bv1, acc[mp][1]);
                acc[mp][2] = ffma2(av[mp], bv2, acc[mp][2]);
                acc[mp][3] = ffma2(av[mp], bv3, acc[mp][3]);
            }
        }

        if (c < 7) {
            #pragma unroll
            for (int j = 0; j < 4; j++) {
                As[nxt][kq * 4 + j][rA]      = ((const float*)&a0)[j];
                As[nxt][kq * 4 + j][rA + 64] = ((const float*)&a1)[j];
            }
            *(float4*)&Bs[nxt][bk][bn] = b;
        }
        __syncthreads();
    }

    // Writeout: 8 rows x 4 cols, one STG.128 per row.
    #pragma unroll
    for (int mp = 0; mp < 4; mp++) {
        float2 c0 = unpack2(acc[mp][0]), c1 = unpack2(acc[mp][1]);
        float2 c2 = unpack2(acc[mp][2]), c3 = unpack2(acc[mp][3]);
        float* o0 = out + (rowBase + m0 + 2 * mp) * (size_t)H_ + colBase + n0;
        float* o1 = o0 + H_;
        *(float4*)o0 = make_float4(c0.x, c1.x, c2.x, c3.x);
        *(float4*)o1 = make_float4(c0.y, c1.y, c2.y, c3.y);
    }
}

// ======================= Phase 2: recurrence =============================
// (unchanged from R6 — 1.62 ms, ~1.5x floor)
// 128 persistent blocks x 512 threads, 4 batches per block.
// h batch-major in smem: hs[k] = float4(h[k, b0..b3]); one broadcast LDS.128
// per k gives both batch-pairs pre-packed for f32x2 FMA.
// Thread (jg = t&63, c = t>>6) owns cols {4jg..4jg+3}, k-range [32c, 32c+32):
//   k-rows 0..15: W in registers as UNDUP float4 (64 regs), dup'ed on ALU
//   k-rows 16..31: W in smem float4 (4 cols), dup'ed on ALU
// Partials exchanged as scalar floats ps[c][b][col].

#define RC_CH    8
#define RC_KR    32
#define RC_KREG  16
#define RC_KSM   16
#define RC_WSM_BYTES (RC_CH * RC_KSM * 64 * 16)   // 131072
#define RC_HS_BYTES  (2 * 256 * 4 * 4)            // 8192
#define RC_PS_BYTES  (RC_CH * 4 * 256 * 4)        // 32768
#define RC_SMEM (RC_WSM_BYTES + RC_HS_BYTES + RC_PS_BYTES)   // 172032

__global__ void __launch_bounds__(512, 1) ctrnn_rec_kernel(
    const float* __restrict__ hidden, const float* __restrict__ Whh,
    float* __restrict__ out, float* __restrict__ tail)
{
    extern __shared__ char smc[];
    float4* Wsm = (float4*)smc;                                // [128][64]
    float*  hsb = (float*)(smc + RC_WSM_BYTES);                // [2][256][4]
    float*  psb = (float*)(smc + RC_WSM_BYTES + RC_HS_BYTES);  // [8][4][256]
    const int t  = threadIdx.x;
    const int jg = t & 63;
    const int c  = t >> 6;
    const int col = t & 255;
    const int hf  = t >> 8;
    const int b0 = blockIdx.x * 4;
    const int k0 = c * RC_KR;

    float4 wreg[RC_KREG];
    #pragma unroll
    for (int i = 0; i < RC_KREG; i++)
        wreg[i] = *(const float4*)(Whh + (size_t)(k0 + i) * H_ + 4 * jg);
    #pragma unroll
    for (int i = 0; i < RC_KSM; i++)
        Wsm[(c * RC_KSM + i) * 64 + jg] =
            *(const float4*)(Whh + (size_t)(k0 + RC_KREG + i) * H_ + 4 * jg);
    if (t < 256) {
        float4 v;
        v.x = hidden[(b0 + 0) * H_ + t];
        v.y = hidden[(b0 + 1) * H_ + t];
        v.z = hidden[(b0 + 2) * H_ + t];
        v.w = hidden[(b0 + 3) * H_ + t];
        ((float4*)hsb)[t] = v;
    }
    __syncthreads();

    const int bA = 2 * hf, bB = 2 * hf + 1;

    for (int s = 0; s < S_; s++) {
        const float* hc = hsb + (s & 1) * 1024;
        float* hn = hsb + ((s & 1) ^ 1) * 1024;
        float* op = out + ((size_t)s * B_ + b0) * H_ + col;

        float xpA = op[bA * 256];
        float xpB = op[bB * 256];

        const ulonglong2* hc2 = (const ulonglong2*)hc;
        u64 acc[4][2];
        #pragma unroll
        for (int cc = 0; cc < 4; cc++) { acc[cc][0] = 0ULL; acc[cc][1] = 0ULL; }

        #pragma unroll
        for (int i = 0; i < RC_KREG; i++) {
            ulonglong2 hv = hc2[k0 + i];
            float4 w4 = wreg[i];
            u64 w0 = pack2(w4.x, w4.x), w1 = pack2(w4.y, w4.y);
            u64 w2 = pack2(w4.z, w4.z), w3 = pack2(w4.w, w4.w);
            acc[0][0] = ffma2(hv.x, w0, acc[0][0]);
            acc[0][1] = ffma2(hv.y, w0, acc[0][1]);
            acc[1][0] = ffma2(hv.x, w1, acc[1][0]);
            acc[1][1] = ffma2(hv.y, w1, acc[1][1]);
            acc[2][0] = ffma2(hv.x, w2, acc[2][0]);
            acc[2][1] = ffma2(hv.y, w2, acc[2][1]);
            acc[3][0] = ffma2(hv.x, w3, acc[3][0]);
            acc[3][1] = ffma2(hv.y, w3, acc[3][1]);
        }
        #pragma unroll
        for (int i = 0; i < RC_KSM; i++) {
            float4 w4 = Wsm[(c * RC_KSM + i) * 64 + jg];
            ulonglong2 hv = hc2[k0 + RC_KREG + i];
            u64 w0 = pack2(w4.x, w4.x), w1 = pack2(w4.y, w4.y);
            u64 w2 = pack2(w4.z, w4.z), w3 = pack2(w4.w, w4.w);
            acc[0][0] = ffma2(hv.x, w0, acc[0][0]);
            acc[0][1] = ffma2(hv.y, w0, acc[0][1]);
            acc[1][0] = ffma2(hv.x, w1, acc[1][0]);
            acc[1][1] = ffma2(hv.y, w1, acc[1][1]);
            acc[2][0] = ffma2(hv.x, w2, acc[2][0]);
            acc[2][1] = ffma2(hv.y, w2, acc[2][1]);
            acc[3][0] = ffma2(hv.x, w3, acc[3][0]);
            acc[3][1] = ffma2(hv.y, w3, acc[3][1]);
        }

        {
            float2 u0a = unpack2(acc[0][0]), u1a = unpack2(acc[1][0]);
            float2 u2a = unpack2(acc[2][0]), u3a = unpack2(acc[3][0]);
            float2 u0b = unpack2(acc[0][1]), u1b = unpack2(acc[1][1]);
            float2 u2b = unpack2(acc[2][1]), u3b = unpack2(acc[3][1]);
            *(float4*)(psb + (c * 4 + 0) * 256 + 4 * jg) =
                make_float4(u0a.x, u1a.x, u2a.x, u3a.x);
            *(float4*)(psb + (c * 4 + 1) * 256 + 4 * jg) =
                make_float4(u0a.y, u1a.y, u2a.y, u3a.y);
            *(float4*)(psb + (c * 4 + 2) * 256 + 4 * jg) =
                make_float4(u0b.x, u1b.x, u2b.x, u3b.x);
            *(float4*)(psb + (c * 4 + 3) * 256 + 4 * jg) =
                make_float4(u0b.y, u1b.y, u2b.y, u3b.y);
        }
        __syncthreads();

        {
            float sA = 0.0f, sB = 0.0f;
            #pragma unroll
            for (int cc = 0; cc < RC_CH; cc++) {
                sA += psb[(cc * 4 + bA) * 256 + col];
                sB += psb[(cc * 4 + bB) * 256 + col];
            }
            float hoA = hc[col * 4 + bA];
            float hoB = hc[col * 4 + bB];
            float hnA = 0.8f * hoA + 0.2f * fmaxf(xpA + sA, 0.0f);
            float hnB = 0.8f * hoB + 0.2f * fmaxf(xpB + sB, 0.0f);
            hn[col * 4 + bA] = hnA;
            hn[col * 4 + bB] = hnB;
            op[bA * 256] = hnA;
            op[bB * 256] = hnB;
        }
        __syncthreads();
    }

    if (tail) {
        tail[(size_t)(b0 + bA) * H_ + col] = hsb[col * 4 + bA];
        tail[(size_t)(b0 + bB) * H_ + col] = hsb[col * 4 + bB];
    }
}

// ============================== launch ===================================

extern "C" void kernel_launch(void* const* d_in, const int* in_sizes, int n_in,
                              void* d_out, int out_size) {
    const float* input  = (const float*)d_in[0];
    const float* hidden = (const float*)d_in[1];
    const float* Win    = (const float*)d_in[2];
    const float* bin    = (const float*)d_in[3];
    const float* Whh    = (const float*)d_in[4];
    const float* bhh    = (const float*)d_in[5];
    float* out = (float*)d_out;

    cudaFuncSetAttribute(ctrnn_rec_kernel,
                         cudaFuncAttributeMaxDynamicSharedMemorySize, RC_SMEM);

    dim3 g(4096, 4);
    xproj_kernel<<<g, 256>>>(input, Win, bin, bhh, out);

    long long main_elems = (long long)S_ * B_ * H_;
    float* tail = ((long long)out_size > main_elems) ? (out + main_elems) : nullptr;
    ctrnn_rec_kernel<<<128, 512, RC_SMEM>>>(hidden, Whh, out, tail);
}